// round 4
// baseline (speedup 1.0000x reference)
#include <cuda_runtime.h>

#define F        512
#define SPLIT    16384
#define NLIL     2048
#define NLAYERS  8
#define NMLIL    8
#define MTOT     (SPLIT + NMLIL * NLIL)   /* 32768 */

#define BM 128
#define BN 128
#define BK 16
#define LDA (BM + 4)
#define LDB (BN + 4)
#define NT  (F / BK)                      /* 32 k-tiles */

// Ping-pong activation scratch (alloc-free rule: __device__ globals).
__device__ float g_ping[(size_t)MTOT * F];
__device__ float g_pong[(size_t)MTOT * F];

__device__ __forceinline__ unsigned long long dup2(float x) {
    unsigned long long r;
    asm("mov.b64 %0, {%1, %1};" : "=l"(r) : "f"(x));
    return r;
}
__device__ __forceinline__ void fma2(unsigned long long& d,
                                     unsigned long long a,
                                     unsigned long long b) {
    asm("fma.rn.f32x2 %0, %1, %2, %0;" : "+l"(d) : "l"(a), "l"(b));
}
__device__ __forceinline__ float2 unpk(unsigned long long v) {
    float lo, hi;
    asm("mov.b64 {%0, %1}, %2;" : "=f"(lo), "=f"(hi) : "l"(v));
    return make_float2(lo, hi);
}

#define STORE_SMEM() do {                                                  \
    As[acol + 0][arow]      = ra0.x; As[acol + 1][arow]      = ra0.y;      \
    As[acol + 2][arow]      = ra0.z; As[acol + 3][arow]      = ra0.w;      \
    As[acol + 0][arow + 64] = ra1.x; As[acol + 1][arow + 64] = ra1.y;      \
    As[acol + 2][arow + 64] = ra1.z; As[acol + 3][arow + 64] = ra1.w;      \
    if (!trans) {                                                          \
        *(float4*)&Bs[brow][bcol]     = rb0;                               \
        *(float4*)&Bs[brow + 8][bcol] = rb1;                               \
    } else {                                                               \
        Bs[acol + 0][arow]      = rb0.x; Bs[acol + 1][arow]      = rb0.y;  \
        Bs[acol + 2][arow]      = rb0.z; Bs[acol + 3][arow]      = rb0.w;  \
        Bs[acol + 0][arow + 64] = rb1.x; Bs[acol + 1][arow + 64] = rb1.y;  \
        Bs[acol + 2][arow + 64] = rb1.z; Bs[acol + 3][arow + 64] = rb1.w;  \
    }                                                                      \
} while (0)

__global__ __launch_bounds__(256, 2)
void layer_kernel(const float* __restrict__ x, float* __restrict__ out,
                  const float* __restrict__ Wbig, const float* __restrict__ Bbig,
                  const float* __restrict__ Wlil, const float* __restrict__ Blil,
                  int layer)
{
    __shared__ __align__(16) float As[BK][LDA];
    __shared__ __align__(16) float Bs[BK][LDB];

    const int tid  = threadIdx.x;
    const int tx   = tid & 15;        // N direction, 16 groups
    const int ty   = tid >> 4;        // M direction, 16 groups
    const int row0 = blockIdx.x * BM;
    const int col0 = blockIdx.y * BN;

    const float* src = (layer == 0) ? x : ((layer & 1) ? g_ping : g_pong);
    float*       dst = (layer == NLAYERS - 1) ? out
                                              : ((layer & 1) ? g_pong : g_ping);

    const float* W;
    const float* bias;
    bool trans;
    if (row0 < SPLIT) {
        // big model: out[n,g] = sum_f A[n,f] * W[f,g]
        W     = Wbig + (size_t)layer * F * F;
        bias  = Bbig + layer * F;
        trans = false;
    } else {
        // little model m: out[n,g] = sum_f A[n,f] * W[g,f]  (transposed)
        int m = (row0 - SPLIT) / NLIL;
        W     = Wlil + (size_t)(layer * NMLIL + m) * F * F;
        bias  = Blil + (layer * NMLIL + m) * F;
        trans = true;
    }

    // Loader coordinates
    const int arow = tid >> 2;           // 0..63  (128x16-style tiles)
    const int acol = (tid & 3) << 2;     // 0,4,8,12
    const int brow = tid >> 5;           // 0..7   (16x128 K-major B tile)
    const int bcol = (tid & 31) << 2;    // 0..124

    const float* aSrc0 = src + (size_t)(row0 + arow) * F + acol;
    const float* aSrc1 = aSrc0 + (size_t)64 * F;
    const float* bSrc0;
    const float* bSrc1;
    if (!trans) {
        bSrc0 = W + (size_t)brow * F + col0 + bcol;   // + kt*F per tile
        bSrc1 = bSrc0 + (size_t)8 * F;
    } else {
        bSrc0 = W + (size_t)(col0 + arow) * F + acol; // + kt per tile
        bSrc1 = bSrc0 + (size_t)64 * F;
    }

    unsigned long long acc[8][4];
#pragma unroll
    for (int i = 0; i < 8; ++i) {
        acc[i][0] = 0ull; acc[i][1] = 0ull; acc[i][2] = 0ull; acc[i][3] = 0ull;
    }

    float4 ra0, ra1, rb0, rb1;

    // Prologue: tile 0
    ra0 = *(const float4*)(aSrc0);
    ra1 = *(const float4*)(aSrc1);
    rb0 = *(const float4*)(bSrc0);
    rb1 = *(const float4*)(bSrc1);
    STORE_SMEM();
    __syncthreads();

    for (int t = 0; t < NT; ++t) {
        const int ktn = (t + 1) * BK;
        if (t + 1 < NT) {
            ra0 = *(const float4*)(aSrc0 + ktn);
            ra1 = *(const float4*)(aSrc1 + ktn);
            if (!trans) {
                rb0 = *(const float4*)(bSrc0 + (size_t)ktn * F);
                rb1 = *(const float4*)(bSrc1 + (size_t)ktn * F);
            } else {
                rb0 = *(const float4*)(bSrc0 + ktn);
                rb1 = *(const float4*)(bSrc1 + ktn);
            }
        }

#pragma unroll
        for (int k = 0; k < BK; ++k) {
            const float4 a0 = *(const float4*)&As[k][ty * 8];
            const float4 a1 = *(const float4*)&As[k][ty * 8 + 4];
            const ulonglong2 b0 = *(const ulonglong2*)&Bs[k][tx * 8];
            const ulonglong2 b1 = *(const ulonglong2*)&Bs[k][tx * 8 + 4];
            float av[8];
            av[0] = a0.x; av[1] = a0.y; av[2] = a0.z; av[3] = a0.w;
            av[4] = a1.x; av[5] = a1.y; av[6] = a1.z; av[7] = a1.w;
#pragma unroll
            for (int i = 0; i < 8; ++i) {
                const unsigned long long ad = dup2(av[i]);
                fma2(acc[i][0], ad, b0.x);
                fma2(acc[i][1], ad, b0.y);
                fma2(acc[i][2], ad, b1.x);
                fma2(acc[i][3], ad, b1.y);
            }
        }
        __syncthreads();
        if (t + 1 < NT) {
            STORE_SMEM();
            __syncthreads();
        }
    }

    // Epilogue: bias add + store
    const float* bptr = bias + col0 + tx * 8;
    const float4 bv0 = *(const float4*)(bptr);
    const float4 bv1 = *(const float4*)(bptr + 4);
    float* drow = dst + (size_t)(row0 + ty * 8) * F + col0 + tx * 8;
#pragma unroll
    for (int i = 0; i < 8; ++i) {
        const float2 c0 = unpk(acc[i][0]);
        const float2 c1 = unpk(acc[i][1]);
        const float2 c2 = unpk(acc[i][2]);
        const float2 c3 = unpk(acc[i][3]);
        float4 o0, o1;
        o0.x = c0.x + bv0.x; o0.y = c0.y + bv0.y;
        o0.z = c1.x + bv0.z; o0.w = c1.y + bv0.w;
        o1.x = c2.x + bv1.x; o1.y = c2.y + bv1.y;
        o1.z = c3.x + bv1.z; o1.w = c3.y + bv1.w;
        *(float4*)(drow)     = o0;
        *(float4*)(drow + 4) = o1;
        drow += F;
    }
}

extern "C" void kernel_launch(void* const* d_in, const int* in_sizes, int n_in,
                              void* d_out, int out_size)
{
    const float* x    = (const float*)d_in[0];
    const float* Wbig = (const float*)d_in[1];
    const float* Bbig = (const float*)d_in[2];
    const float* Wlil = (const float*)d_in[3];
    const float* Blil = (const float*)d_in[4];
    float* out = (float*)d_out;

    dim3 grid(MTOT / BM, F / BN);   // 256 x 4 = 1024 blocks
    dim3 block(256);
    for (int l = 0; l < NLAYERS; ++l) {
        layer_kernel<<<grid, block>>>(x, out, Wbig, Bbig, Wlil, Blil, l);
    }
}

// round 6
// speedup vs baseline: 1.0016x; 1.0016x over previous
#include <cuda_runtime.h>

#define F        512
#define SPLIT    16384
#define NLIL     2048
#define NLAYERS  8
#define NMLIL    8
#define MTOT     (SPLIT + NMLIL * NLIL)   /* 32768 */

#define BM 128
#define BN 128
#define BK 16
#define LDA (BM + 4)
#define LDB (BN + 4)
#define NT  (F / BK)                      /* 32 k-tiles */

// Ping-pong activation scratch (alloc-free rule: __device__ globals).
__device__ float g_ping[(size_t)MTOT * F];
__device__ float g_pong[(size_t)MTOT * F];

__device__ __forceinline__ unsigned long long dup2(float x) {
    unsigned long long r;
    asm("mov.b64 %0, {%1, %1};" : "=l"(r) : "f"(x));
    return r;
}
__device__ __forceinline__ void fma2(unsigned long long& d,
                                     unsigned long long a,
                                     unsigned long long b) {
    asm("fma.rn.f32x2 %0, %1, %2, %0;" : "+l"(d) : "l"(a), "l"(b));
}
__device__ __forceinline__ float2 unpk(unsigned long long v) {
    float lo, hi;
    asm("mov.b64 {%0, %1}, %2;" : "=f"(lo), "=f"(hi) : "l"(v));
    return make_float2(lo, hi);
}

#define STORE_SMEM() do {                                                  \
    As[acol + 0][arow]      = ra0.x; As[acol + 1][arow]      = ra0.y;      \
    As[acol + 2][arow]      = ra0.z; As[acol + 3][arow]      = ra0.w;      \
    As[acol + 0][arow + 64] = ra1.x; As[acol + 1][arow + 64] = ra1.y;      \
    As[acol + 2][arow + 64] = ra1.z; As[acol + 3][arow + 64] = ra1.w;      \
    if (!trans) {                                                          \
        *(float4*)&Bs[brow][bcol]     = rb0;                               \
        *(float4*)&Bs[brow + 8][bcol] = rb1;                               \
    } else {                                                               \
        Bs[acol + 0][arow]      = rb0.x; Bs[acol + 1][arow]      = rb0.y;  \
        Bs[acol + 2][arow]      = rb0.z; Bs[acol + 3][arow]      = rb0.w;  \
        Bs[acol + 0][arow + 64] = rb1.x; Bs[acol + 1][arow + 64] = rb1.y;  \
        Bs[acol + 2][arow + 64] = rb1.z; Bs[acol + 3][arow + 64] = rb1.w;  \
    }                                                                      \
} while (0)

__global__ __launch_bounds__(256, 2)
void layer_kernel(const float* __restrict__ x, float* __restrict__ out,
                  const float* __restrict__ Wbig, const float* __restrict__ Bbig,
                  const float* __restrict__ Wlil, const float* __restrict__ Blil,
                  int layer)
{
    __shared__ __align__(16) float As[BK][LDA];
    __shared__ __align__(16) float Bs[BK][LDB];

    const int tid  = threadIdx.x;
    const int tx   = tid & 15;        // N direction, 16 groups
    const int ty   = tid >> 4;        // M direction, 16 groups
    const int row0 = blockIdx.x * BM;
    const int col0 = blockIdx.y * BN;

    const float* src = (layer == 0) ? x : ((layer & 1) ? g_ping : g_pong);
    float*       dst = (layer == NLAYERS - 1) ? out
                                              : ((layer & 1) ? g_pong : g_ping);

    const float* W;
    const float* bias;
    bool trans;
    if (row0 < SPLIT) {
        // big model: out[n,g] = sum_f A[n,f] * W[f,g]
        W     = Wbig + (size_t)layer * F * F;
        bias  = Bbig + layer * F;
        trans = false;
    } else {
        // little model m: out[n,g] = sum_f A[n,f] * W[g,f]  (transposed)
        int m = (row0 - SPLIT) / NLIL;
        W     = Wlil + (size_t)(layer * NMLIL + m) * F * F;
        bias  = Blil + (layer * NMLIL + m) * F;
        trans = true;
    }

    // Loader coordinates
    const int arow = tid >> 2;           // 0..63  (128x16-style tiles)
    const int acol = (tid & 3) << 2;     // 0,4,8,12
    const int brow = tid >> 5;           // 0..7   (16x128 K-major B tile)
    const int bcol = (tid & 31) << 2;    // 0..124

    const float* aSrc0 = src + (size_t)(row0 + arow) * F + acol;
    const float* aSrc1 = aSrc0 + (size_t)64 * F;
    const float* bSrc0;
    const float* bSrc1;
    if (!trans) {
        bSrc0 = W + (size_t)brow * F + col0 + bcol;   // + kt*F per tile
        bSrc1 = bSrc0 + (size_t)8 * F;
    } else {
        bSrc0 = W + (size_t)(col0 + arow) * F + acol; // + kt per tile
        bSrc1 = bSrc0 + (size_t)64 * F;
    }

    unsigned long long acc[8][4];
#pragma unroll
    for (int i = 0; i < 8; ++i) {
        acc[i][0] = 0ull; acc[i][1] = 0ull; acc[i][2] = 0ull; acc[i][3] = 0ull;
    }

    float4 ra0, ra1, rb0, rb1;

    // Prologue: tile 0
    ra0 = *(const float4*)(aSrc0);
    ra1 = *(const float4*)(aSrc1);
    rb0 = *(const float4*)(bSrc0);
    rb1 = *(const float4*)(bSrc1);
    STORE_SMEM();
    __syncthreads();

    for (int t = 0; t < NT; ++t) {
        const int ktn = (t + 1) * BK;
        if (t + 1 < NT) {
            ra0 = *(const float4*)(aSrc0 + ktn);
            ra1 = *(const float4*)(aSrc1 + ktn);
            if (!trans) {
                rb0 = *(const float4*)(bSrc0 + (size_t)ktn * F);
                rb1 = *(const float4*)(bSrc1 + (size_t)ktn * F);
            } else {
                rb0 = *(const float4*)(bSrc0 + ktn);
                rb1 = *(const float4*)(bSrc1 + ktn);
            }
        }

#pragma unroll
        for (int k = 0; k < BK; ++k) {
            const float4 a0 = *(const float4*)&As[k][ty * 8];
            const float4 a1 = *(const float4*)&As[k][ty * 8 + 4];
            const ulonglong2 b0 = *(const ulonglong2*)&Bs[k][tx * 8];
            const ulonglong2 b1 = *(const ulonglong2*)&Bs[k][tx * 8 + 4];
            float av[8];
            av[0] = a0.x; av[1] = a0.y; av[2] = a0.z; av[3] = a0.w;
            av[4] = a1.x; av[5] = a1.y; av[6] = a1.z; av[7] = a1.w;
#pragma unroll
            for (int i = 0; i < 8; ++i) {
                const unsigned long long ad = dup2(av[i]);
                fma2(acc[i][0], ad, b0.x);
                fma2(acc[i][1], ad, b0.y);
                fma2(acc[i][2], ad, b1.x);
                fma2(acc[i][3], ad, b1.y);
            }
        }
        __syncthreads();
        if (t + 1 < NT) {
            STORE_SMEM();
            __syncthreads();
        }
    }

    // Epilogue: bias add + store
    const float* bptr = bias + col0 + tx * 8;
    const float4 bv0 = *(const float4*)(bptr);
    const float4 bv1 = *(const float4*)(bptr + 4);
    float* drow = dst + (size_t)(row0 + ty * 8) * F + col0 + tx * 8;
#pragma unroll
    for (int i = 0; i < 8; ++i) {
        const float2 c0 = unpk(acc[i][0]);
        const float2 c1 = unpk(acc[i][1]);
        const float2 c2 = unpk(acc[i][2]);
        const float2 c3 = unpk(acc[i][3]);
        float4 o0, o1;
        o0.x = c0.x + bv0.x; o0.y = c0.y + bv0.y;
        o0.z = c1.x + bv0.z; o0.w = c1.y + bv0.w;
        o1.x = c2.x + bv1.x; o1.y = c2.y + bv1.y;
        o1.z = c3.x + bv1.z; o1.w = c3.y + bv1.w;
        *(float4*)(drow)     = o0;
        *(float4*)(drow + 4) = o1;
        drow += F;
    }
}

extern "C" void kernel_launch(void* const* d_in, const int* in_sizes, int n_in,
                              void* d_out, int out_size)
{
    const float* x    = (const float*)d_in[0];
    const float* Wbig = (const float*)d_in[1];
    const float* Bbig = (const float*)d_in[2];
    const float* Wlil = (const float*)d_in[3];
    const float* Blil = (const float*)d_in[4];
    float* out = (float*)d_out;

    dim3 grid(MTOT / BM, F / BN);   // 256 x 4 = 1024 blocks
    dim3 block(256);
    for (int l = 0; l < NLAYERS; ++l) {
        layer_kernel<<<grid, block>>>(x, out, Wbig, Bbig, Wlil, Blil, l);
    }
}

// round 10
// speedup vs baseline: 1.0902x; 1.0884x over previous
#include <cuda_runtime.h>
#include <cstdint>

#define F        512
#define SPLIT    16384
#define NLIL     2048
#define NLAYERS  8
#define NMLIL    8
#define MTOT     (SPLIT + NMLIL * NLIL)   /* 32768 */

#define BM   128
#define BN   128
#define KC   32
#define NCH  (F / KC)                     /* 16 chunks */

#define LDSW 36                           /* smem row stride in floats (pad 4) */
#define A_FLOATS (BM * LDSW)              /* 4608 */
#define B_FLOATS (BN * LDSW)              /* 4608 */
#define STG_FLOATS (A_FLOATS + B_FLOATS)  /* 9216 floats = 36864 B */
#define SMEM_DYN (2 * STG_FLOATS * 4)     /* 73728 B */

__device__ float g_ping[(size_t)MTOT * F];
__device__ float g_pong[(size_t)MTOT * F];
__device__ float g_WT[(size_t)NLAYERS * F * F];

/* ---------------- helpers ---------------- */
__device__ __forceinline__ uint32_t smem_u32(const void* p) {
    uint32_t a;
    asm("{ .reg .u64 t; cvta.to.shared.u64 t, %1; cvt.u32.u64 %0, t; }" : "=r"(a) : "l"(p));
    return a;
}
__device__ __forceinline__ void cpasync16(uint32_t s, const void* g) {
    asm volatile("cp.async.cg.shared.global [%0], [%1], 16;" :: "r"(s), "l"(g) : "memory");
}
#define CP_COMMIT() asm volatile("cp.async.commit_group;" ::: "memory")
#define CP_WAIT(n)  asm volatile("cp.async.wait_group %0;" :: "n"(n) : "memory")

__device__ __forceinline__ void split_tf32(float v, uint32_t& h, uint32_t& l) {
    asm("cvt.rna.tf32.f32 %0, %1;" : "=r"(h) : "f"(v));
    float lo = v - __uint_as_float(h);
    asm("cvt.rna.tf32.f32 %0, %1;" : "=r"(l) : "f"(lo));
}
__device__ __forceinline__ void mma8(float* c, const uint32_t* a, uint32_t b0, uint32_t b1) {
    asm volatile(
        "mma.sync.aligned.m16n8k8.row.col.f32.tf32.tf32.f32 "
        "{%0,%1,%2,%3}, {%4,%5,%6,%7}, {%8,%9}, {%0,%1,%2,%3};"
        : "+f"(c[0]), "+f"(c[1]), "+f"(c[2]), "+f"(c[3])
        : "r"(a[0]), "r"(a[1]), "r"(a[2]), "r"(a[3]), "r"(b0), "r"(b1));
}

/* -------- Wbig transpose: WT[l][g][f] = W[l][f][g] (so B is [N,K]) -------- */
__global__ void transpose_wbig(const float* __restrict__ W, float* __restrict__ WT) {
    __shared__ float t[32][33];
    int l = blockIdx.z;
    int f0 = blockIdx.x * 32, g0 = blockIdx.y * 32;
    int x = threadIdx.x, y = threadIdx.y;
    const float* Wl = W + (size_t)l * F * F;
    float* WTl = WT + (size_t)l * F * F;
#pragma unroll
    for (int r = 0; r < 32; r += 8)
        t[y + r][x] = Wl[(size_t)(f0 + y + r) * F + g0 + x];
    __syncthreads();
#pragma unroll
    for (int r = 0; r < 32; r += 8)
        WTl[(size_t)(g0 + y + r) * F + f0 + x] = t[x][y + r];
}

/* ------------------------- per-layer GEMM ------------------------- */
__global__ __launch_bounds__(256)
void layer_kernel(const float* __restrict__ src, float* __restrict__ dst,
                  const float* __restrict__ WT, const float* __restrict__ Bbig,
                  const float* __restrict__ Wlil, const float* __restrict__ Blil,
                  int layer)
{
    extern __shared__ float smem[];
    const int tid  = threadIdx.x;
    const int warp = tid >> 5;
    const int lane = tid & 31;
    const int wm   = warp >> 2;         /* 0..1 : 64-row slab  */
    const int wn   = warp & 3;          /* 0..3 : 32-col slab  */
    const int row0 = blockIdx.x * BM;
    const int n0   = blockIdx.y * BN;

    const float* wsrc;
    const float* bias;
    if (row0 < SPLIT) {
        wsrc = WT + (size_t)layer * F * F + (size_t)n0 * F;
        bias = Bbig + layer * F + n0;
    } else {
        int mi = (row0 - SPLIT) / NLIL;
        wsrc = Wlil + (size_t)(layer * NMLIL + mi) * F * F + (size_t)n0 * F;
        bias = Blil + (layer * NMLIL + mi) * F + n0;
    }
    const float* asrc = src + (size_t)row0 * F;

    const uint32_t sb = smem_u32(smem);

    /* --- cp.async staging: thread pair per row; 4x16B chunks per thread --- */
    const int srow = tid >> 1;                  /* 0..127 */
    const int shalf = (tid & 1) * 16;           /* float offset within 32-col row */
    const uint32_t sA = sb + (srow * LDSW + shalf) * 4;
    const uint32_t sB = sA + A_FLOATS * 4;
    const float* gA = asrc + (size_t)srow * F + shalf;
    const float* gB = wsrc + (size_t)srow * F + shalf;

    auto issue = [&](int t) {
        const uint32_t so = (uint32_t)((t & 1) * STG_FLOATS * 4);
        const int k0 = t * KC;
#pragma unroll
        for (int c = 0; c < 4; ++c)
            cpasync16(sA + so + c * 16, gA + k0 + c * 4);
#pragma unroll
        for (int c = 0; c < 4; ++c)
            cpasync16(sB + so + c * 16, gB + k0 + c * 4);
        CP_COMMIT();
    };

    float acc[4][4][4];
#pragma unroll
    for (int i = 0; i < 4; ++i)
#pragma unroll
        for (int j = 0; j < 4; ++j) {
            acc[i][j][0] = 0.f; acc[i][j][1] = 0.f;
            acc[i][j][2] = 0.f; acc[i][j][3] = 0.f;
        }

    const int lr = lane >> 2;   /* 0..7 */
    const int lc = lane & 3;    /* 0..3 */

    issue(0);

    for (int t = 0; t < NCH; ++t) {
        if (t + 1 < NCH) { issue(t + 1); CP_WAIT(1); }
        else             { CP_WAIT(0); }
        __syncthreads();

        const float* As = smem + (t & 1) * STG_FLOATS;
        const float* Bs = As + A_FLOATS;

#pragma unroll
        for (int ks = 0; ks < 4; ++ks) {
            const int kb = ks * 8;
            /* A fragments: 4 m-tiles, split hi/lo in registers */
            uint32_t ah[4][4], al[4][4];
#pragma unroll
            for (int mt = 0; mt < 4; ++mt) {
                const int r0 = wm * 64 + mt * 16 + lr;
                const float v0 = As[r0 * LDSW + kb + lc];
                const float v1 = As[(r0 + 8) * LDSW + kb + lc];
                const float v2 = As[r0 * LDSW + kb + 4 + lc];
                const float v3 = As[(r0 + 8) * LDSW + kb + 4 + lc];
                split_tf32(v0, ah[mt][0], al[mt][0]);
                split_tf32(v1, ah[mt][1], al[mt][1]);
                split_tf32(v2, ah[mt][2], al[mt][2]);
                split_tf32(v3, ah[mt][3], al[mt][3]);
            }
#pragma unroll
            for (int nt = 0; nt < 4; ++nt) {
                const int nr = wn * 32 + nt * 8 + lr;
                const float u0 = Bs[nr * LDSW + kb + lc];
                const float u1 = Bs[nr * LDSW + kb + 4 + lc];
                uint32_t bh0, bl0, bh1, bl1;
                split_tf32(u0, bh0, bl0);
                split_tf32(u1, bh1, bl1);
#pragma unroll
                for (int mt = 0; mt < 4; ++mt) {
                    mma8(acc[mt][nt], ah[mt], bh0, bh1);  /* Ah*Bh */
                    mma8(acc[mt][nt], al[mt], bh0, bh1);  /* Al*Bh */
                    mma8(acc[mt][nt], ah[mt], bl0, bl1);  /* Ah*Bl */
                }
            }
        }
        __syncthreads();   /* everyone done reading buf t&1 before it is refilled */
    }

    /* ---------------- epilogue: bias + store ---------------- */
#pragma unroll
    for (int mt = 0; mt < 4; ++mt) {
        const int r = row0 + wm * 64 + mt * 16 + lr;
#pragma unroll
        for (int nt = 0; nt < 4; ++nt) {
            const int nloc = wn * 32 + nt * 8 + lc * 2;
            const float bx = bias[nloc];
            const float by = bias[nloc + 1];
            float2 o0, o1;
            o0.x = acc[mt][nt][0] + bx; o0.y = acc[mt][nt][1] + by;
            o1.x = acc[mt][nt][2] + bx; o1.y = acc[mt][nt][3] + by;
            *(float2*)(dst + (size_t)r * F + n0 + nloc)       = o0;
            *(float2*)(dst + (size_t)(r + 8) * F + n0 + nloc) = o1;
        }
    }
}

/* ------------------------------ host ------------------------------ */
extern "C" void kernel_launch(void* const* d_in, const int* in_sizes, int n_in,
                              void* d_out, int out_size)
{
    const float* x    = (const float*)d_in[0];
    const float* Wbig = (const float*)d_in[1];
    const float* Bbig = (const float*)d_in[2];
    const float* Wlil = (const float*)d_in[3];
    const float* Blil = (const float*)d_in[4];
    float* out = (float*)d_out;

    float *ping, *pong, *wt;
    cudaGetSymbolAddress((void**)&ping, g_ping);
    cudaGetSymbolAddress((void**)&pong, g_pong);
    cudaGetSymbolAddress((void**)&wt, g_WT);

    cudaFuncSetAttribute(layer_kernel,
                         cudaFuncAttributeMaxDynamicSharedMemorySize, SMEM_DYN);

    transpose_wbig<<<dim3(16, 16, 8), dim3(32, 8)>>>(Wbig, wt);

    dim3 grid(MTOT / BM, F / BN);   /* 256 x 4 */
    for (int l = 0; l < NLAYERS; ++l) {
        const float* s = (l == 0) ? x : ((l & 1) ? ping : pong);
        float* d = (l == NLAYERS - 1) ? out : ((l & 1) ? pong : ping);
        layer_kernel<<<grid, 256, SMEM_DYN>>>(s, d, wt, Bbig, Wlil, Blil, l);
    }
}

// round 11
// speedup vs baseline: 1.1931x; 1.0945x over previous
#include <cuda_runtime.h>
#include <cstdint>

#define F        512
#define SPLIT    16384
#define NLIL     2048
#define NLAYERS  8
#define NMLIL    8
#define MTOT     (SPLIT + NMLIL * NLIL)   /* 32768 */

#define BM   128
#define BN   128
#define KC   32
#define NCH  (F / KC)                     /* 16 chunks */

#define LDSW 36                           /* smem row stride in floats (pad 4) */
#define TILE_FLOATS (BM * LDSW)           /* 4608 */
#define STG_FLOATS  (4 * TILE_FLOATS)     /* Ah, Al, Bh, Bl */
#define SMEM_DYN (2 * STG_FLOATS * 4)     /* 147456 B */

#define OFF_AH 0
#define OFF_AL (TILE_FLOATS)
#define OFF_BH (2 * TILE_FLOATS)
#define OFF_BL (3 * TILE_FLOATS)

__device__ float g_ping[(size_t)MTOT * F];
__device__ float g_pong[(size_t)MTOT * F];
__device__ float g_WT[(size_t)NLAYERS * F * F];

/* ---------------- helpers ---------------- */
__device__ __forceinline__ void split_tf32(float v, uint32_t& h, uint32_t& l) {
    asm("cvt.rna.tf32.f32 %0, %1;" : "=r"(h) : "f"(v));
    float lo = v - __uint_as_float(h);
    asm("cvt.rna.tf32.f32 %0, %1;" : "=r"(l) : "f"(lo));
}
__device__ __forceinline__ void mma8(float* c, const uint32_t* a, uint32_t b0, uint32_t b1) {
    asm volatile(
        "mma.sync.aligned.m16n8k8.row.col.f32.tf32.tf32.f32 "
        "{%0,%1,%2,%3}, {%4,%5,%6,%7}, {%8,%9}, {%0,%1,%2,%3};"
        : "+f"(c[0]), "+f"(c[1]), "+f"(c[2]), "+f"(c[3])
        : "r"(a[0]), "r"(a[1]), "r"(a[2]), "r"(a[3]), "r"(b0), "r"(b1));
}

/* -------- Wbig transpose: WT[l][g][f] = W[l][f][g] (so B is [N,K]) -------- */
__global__ void transpose_wbig(const float* __restrict__ W, float* __restrict__ WT) {
    __shared__ float t[32][33];
    int l = blockIdx.z;
    int f0 = blockIdx.x * 32, g0 = blockIdx.y * 32;
    int x = threadIdx.x, y = threadIdx.y;
    const float* Wl = W + (size_t)l * F * F;
    float* WTl = WT + (size_t)l * F * F;
#pragma unroll
    for (int r = 0; r < 32; r += 8)
        t[y + r][x] = Wl[(size_t)(f0 + y + r) * F + g0 + x];
    __syncthreads();
#pragma unroll
    for (int r = 0; r < 32; r += 8)
        WTl[(size_t)(g0 + y + r) * F + f0 + x] = t[x][y + r];
}

/* ------------------------- per-layer GEMM ------------------------- */
__global__ __launch_bounds__(256, 1)
void layer_kernel(const float* __restrict__ src, float* __restrict__ dst,
                  const float* __restrict__ WT, const float* __restrict__ Bbig,
                  const float* __restrict__ Wlil, const float* __restrict__ Blil,
                  int layer)
{
    extern __shared__ float smem[];
    const int tid  = threadIdx.x;
    const int warp = tid >> 5;
    const int lane = tid & 31;
    const int wm   = warp >> 2;         /* 0..1 : 64-row slab  */
    const int wn   = warp & 3;          /* 0..3 : 32-col slab  */
    const int row0 = blockIdx.x * BM;
    const int n0   = blockIdx.y * BN;

    const float* wsrc;
    const float* bias;
    if (row0 < SPLIT) {
        wsrc = WT + (size_t)layer * F * F + (size_t)n0 * F;
        bias = Bbig + layer * F + n0;
    } else {
        int mi = (row0 - SPLIT) / NLIL;
        wsrc = Wlil + (size_t)(layer * NMLIL + mi) * F * F + (size_t)n0 * F;
        bias = Blil + (layer * NMLIL + mi) * F + n0;
    }
    const float* asrc = src + (size_t)row0 * F;

    /* --- staging coordinates: thread pair per row; 4 float4 per tile --- */
    const int srow  = tid >> 1;                 /* 0..127 */
    const int shalf = (tid & 1) * 16;           /* float offset within 32-col row */
    const float* gA = asrc + (size_t)srow * F + shalf;
    const float* gB = wsrc + (size_t)srow * F + shalf;
    const int sbase = srow * LDSW + shalf;

    float4 pa[4], pb[4];

    auto ldg_chunk = [&](int t) {
        const int k0 = t * KC;
#pragma unroll
        for (int c = 0; c < 4; ++c) {
            pa[c] = *(const float4*)(gA + k0 + c * 4);
            pb[c] = *(const float4*)(gB + k0 + c * 4);
        }
    };
    auto sts_chunk = [&](int t) {
        float* st = smem + (t & 1) * STG_FLOATS;
#pragma unroll
        for (int c = 0; c < 4; ++c) {
            uint4 h, l;
            split_tf32(pa[c].x, h.x, l.x); split_tf32(pa[c].y, h.y, l.y);
            split_tf32(pa[c].z, h.z, l.z); split_tf32(pa[c].w, h.w, l.w);
            *(uint4*)(st + OFF_AH + sbase + c * 4) = h;
            *(uint4*)(st + OFF_AL + sbase + c * 4) = l;
            split_tf32(pb[c].x, h.x, l.x); split_tf32(pb[c].y, h.y, l.y);
            split_tf32(pb[c].z, h.z, l.z); split_tf32(pb[c].w, h.w, l.w);
            *(uint4*)(st + OFF_BH + sbase + c * 4) = h;
            *(uint4*)(st + OFF_BL + sbase + c * 4) = l;
        }
    };

    float acc[4][4][4];
#pragma unroll
    for (int i = 0; i < 4; ++i)
#pragma unroll
        for (int j = 0; j < 4; ++j) {
            acc[i][j][0] = 0.f; acc[i][j][1] = 0.f;
            acc[i][j][2] = 0.f; acc[i][j][3] = 0.f;
        }

    const int lr = lane >> 2;   /* 0..7 */
    const int lc = lane & 3;    /* 0..3 */

    /* prologue */
    ldg_chunk(0);
    sts_chunk(0);
    __syncthreads();

    for (int t = 0; t < NCH; ++t) {
        if (t + 1 < NCH) ldg_chunk(t + 1);   /* LDG early, hidden behind MMAs */

        const uint32_t* stg = (const uint32_t*)(smem + (t & 1) * STG_FLOATS);
        const uint32_t* AsH = stg + OFF_AH;
        const uint32_t* AsL = stg + OFF_AL;
        const uint32_t* BsH = stg + OFF_BH;
        const uint32_t* BsL = stg + OFF_BL;

#pragma unroll
        for (int ks = 0; ks < 4; ++ks) {
            const int kb = ks * 8;
            /* A fragments: pre-split, no ALU */
            uint32_t ah[4][4], al[4][4];
#pragma unroll
            for (int mt = 0; mt < 4; ++mt) {
                const int r0 = wm * 64 + mt * 16 + lr;
                const int i00 = r0 * LDSW + kb + lc;
                const int i10 = (r0 + 8) * LDSW + kb + lc;
                ah[mt][0] = AsH[i00];     al[mt][0] = AsL[i00];
                ah[mt][1] = AsH[i10];     al[mt][1] = AsL[i10];
                ah[mt][2] = AsH[i00 + 4]; al[mt][2] = AsL[i00 + 4];
                ah[mt][3] = AsH[i10 + 4]; al[mt][3] = AsL[i10 + 4];
            }
#pragma unroll
            for (int nt = 0; nt < 4; ++nt) {
                const int nr = wn * 32 + nt * 8 + lr;
                const int j0 = nr * LDSW + kb + lc;
                const uint32_t bh0 = BsH[j0], bh1 = BsH[j0 + 4];
                const uint32_t bl0 = BsL[j0], bl1 = BsL[j0 + 4];
                /* term-outer, mt-inner: consecutive MMAs hit different accs */
#pragma unroll
                for (int mt = 0; mt < 4; ++mt) mma8(acc[mt][nt], ah[mt], bh0, bh1);
#pragma unroll
                for (int mt = 0; mt < 4; ++mt) mma8(acc[mt][nt], al[mt], bh0, bh1);
#pragma unroll
                for (int mt = 0; mt < 4; ++mt) mma8(acc[mt][nt], ah[mt], bl0, bl1);
            }
        }

        if (t + 1 < NCH) {
            sts_chunk(t + 1);          /* writes other buffer: no hazard w/ readers of t */
        }
        __syncthreads();
    }

    /* ---------------- epilogue: bias + store ---------------- */
#pragma unroll
    for (int mt = 0; mt < 4; ++mt) {
        const int r = row0 + wm * 64 + mt * 16 + lr;
#pragma unroll
        for (int nt = 0; nt < 4; ++nt) {
            const int nloc = wn * 32 + nt * 8 + lc * 2;
            const float bx = bias[nloc];
            const float by = bias[nloc + 1];
            float2 o0, o1;
            o0.x = acc[mt][nt][0] + bx; o0.y = acc[mt][nt][1] + by;
            o1.x = acc[mt][nt][2] + bx; o1.y = acc[mt][nt][3] + by;
            *(float2*)(dst + (size_t)r * F + n0 + nloc)       = o0;
            *(float2*)(dst + (size_t)(r + 8) * F + n0 + nloc) = o1;
        }
    }
}

/* ------------------------------ host ------------------------------ */
extern "C" void kernel_launch(void* const* d_in, const int* in_sizes, int n_in,
                              void* d_out, int out_size)
{
    const float* x    = (const float*)d_in[0];
    const float* Wbig = (const float*)d_in[1];
    const float* Bbig = (const float*)d_in[2];
    const float* Wlil = (const float*)d_in[3];
    const float* Blil = (const float*)d_in[4];
    float* out = (float*)d_out;

    float *ping, *pong, *wt;
    cudaGetSymbolAddress((void**)&ping, g_ping);
    cudaGetSymbolAddress((void**)&pong, g_pong);
    cudaGetSymbolAddress((void**)&wt, g_WT);

    cudaFuncSetAttribute(layer_kernel,
                         cudaFuncAttributeMaxDynamicSharedMemorySize, SMEM_DYN);

    transpose_wbig<<<dim3(16, 16, 8), dim3(32, 8)>>>(Wbig, wt);

    dim3 grid(MTOT / BM, F / BN);   /* 256 x 4 */
    for (int l = 0; l < NLAYERS; ++l) {
        const float* s = (l == 0) ? x : ((l & 1) ? ping : pong);
        float* d = (l == NLAYERS - 1) ? out : ((l & 1) ? pong : ping);
        layer_kernel<<<grid, 256, SMEM_DYN>>>(s, d, wt, Bbig, Wlil, Blil, l);
    }
}

// round 12
// speedup vs baseline: 1.2690x; 1.0636x over previous
#include <cuda_runtime.h>
#include <cstdint>

#define F        512
#define SPLIT    16384
#define NLIL     2048
#define NLAYERS  8
#define NMLIL    8
#define MTOT     (SPLIT + NMLIL * NLIL)   /* 32768 */

#define BM   128
#define BN   128
#define KC   32
#define NCH  (F / KC)                     /* 16 chunks */

#define LDSW 36                           /* smem row stride in floats (pad 4) */
#define TILE_FLOATS (BM * LDSW)           /* 4608 */
#define STG_FLOATS  (3 * TILE_FLOATS)     /* Ah, Al, Braw */
#define SMEM_DYN (2 * STG_FLOATS * 4)     /* 110592 B -> 2 CTAs/SM */

#define OFF_AH 0
#define OFF_AL (TILE_FLOATS)
#define OFF_B  (2 * TILE_FLOATS)

__device__ float g_ping[(size_t)MTOT * F];
__device__ float g_pong[(size_t)MTOT * F];
__device__ float g_WT[(size_t)NLAYERS * F * F];

/* ---------------- helpers ---------------- */
__device__ __forceinline__ uint32_t smem_u32(const void* p) {
    uint32_t a;
    asm("{ .reg .u64 t; cvta.to.shared.u64 t, %1; cvt.u32.u64 %0, t; }" : "=r"(a) : "l"(p));
    return a;
}
__device__ __forceinline__ void cpasync16(uint32_t s, const void* g) {
    asm volatile("cp.async.cg.shared.global [%0], [%1], 16;" :: "r"(s), "l"(g) : "memory");
}
#define CP_COMMIT() asm volatile("cp.async.commit_group;" ::: "memory")
#define CP_WAIT0()  asm volatile("cp.async.wait_group 0;" ::: "memory")

__device__ __forceinline__ void split_tf32(float v, uint32_t& h, uint32_t& l) {
    asm("cvt.rna.tf32.f32 %0, %1;" : "=r"(h) : "f"(v));
    float lo = v - __uint_as_float(h);
    asm("cvt.rna.tf32.f32 %0, %1;" : "=r"(l) : "f"(lo));
}
__device__ __forceinline__ void mma8(float* c, const uint32_t* a, uint32_t b0, uint32_t b1) {
    asm volatile(
        "mma.sync.aligned.m16n8k8.row.col.f32.tf32.tf32.f32 "
        "{%0,%1,%2,%3}, {%4,%5,%6,%7}, {%8,%9}, {%0,%1,%2,%3};"
        : "+f"(c[0]), "+f"(c[1]), "+f"(c[2]), "+f"(c[3])
        : "r"(a[0]), "r"(a[1]), "r"(a[2]), "r"(a[3]), "r"(b0), "r"(b1));
}

/* -------- Wbig transpose: WT[l][g][f] = W[l][f][g] (so B is [N,K]) -------- */
__global__ void transpose_wbig(const float* __restrict__ W, float* __restrict__ WT) {
    __shared__ float t[32][33];
    int l = blockIdx.z;
    int f0 = blockIdx.x * 32, g0 = blockIdx.y * 32;
    int x = threadIdx.x, y = threadIdx.y;
    const float* Wl = W + (size_t)l * F * F;
    float* WTl = WT + (size_t)l * F * F;
#pragma unroll
    for (int r = 0; r < 32; r += 8)
        t[y + r][x] = Wl[(size_t)(f0 + y + r) * F + g0 + x];
    __syncthreads();
#pragma unroll
    for (int r = 0; r < 32; r += 8)
        WTl[(size_t)(g0 + y + r) * F + f0 + x] = t[x][y + r];
}

/* ------------------------- per-layer GEMM ------------------------- */
__global__ __launch_bounds__(256, 2)
void layer_kernel(const float* __restrict__ src, float* __restrict__ dst,
                  const float* __restrict__ WT, const float* __restrict__ Bbig,
                  const float* __restrict__ Wlil, const float* __restrict__ Blil,
                  int layer)
{
    extern __shared__ float smem[];
    const int tid  = threadIdx.x;
    const int warp = tid >> 5;
    const int lane = tid & 31;
    const int wm   = warp >> 2;         /* 0..1 : 64-row slab  */
    const int wn   = warp & 3;          /* 0..3 : 32-col slab  */
    const int row0 = blockIdx.x * BM;
    const int n0   = blockIdx.y * BN;

    const float* wsrc;
    const float* bias;
    if (row0 < SPLIT) {
        wsrc = WT + (size_t)layer * F * F + (size_t)n0 * F;
        bias = Bbig + layer * F + n0;
    } else {
        int mi = (row0 - SPLIT) / NLIL;
        wsrc = Wlil + (size_t)(layer * NMLIL + mi) * F * F + (size_t)n0 * F;
        bias = Blil + (layer * NMLIL + mi) * F + n0;
    }
    const float* asrc = src + (size_t)row0 * F;

    const uint32_t sb = smem_u32(smem);

    /* --- staging coordinates: thread pair per row; 4 float4 per tile --- */
    const int srow  = tid >> 1;                 /* 0..127 */
    const int shalf = (tid & 1) * 16;           /* float offset within 32-col row */
    const float* gA = asrc + (size_t)srow * F + shalf;
    const float* gB = wsrc + (size_t)srow * F + shalf;
    const int sbase = srow * LDSW + shalf;

    float4 pa[4];

    auto issueB = [&](int t) {                  /* cp.async raw fp32 B tile */
        const int k0 = t * KC;
        const uint32_t so = sb + (uint32_t)(((t & 1) * STG_FLOATS) + OFF_B + sbase) * 4;
#pragma unroll
        for (int c = 0; c < 4; ++c)
            cpasync16(so + c * 16, gB + k0 + c * 4);
        CP_COMMIT();
    };
    auto ldgA = [&](int t) {
        const int k0 = t * KC;
#pragma unroll
        for (int c = 0; c < 4; ++c)
            pa[c] = *(const float4*)(gA + k0 + c * 4);
    };
    auto stsA = [&](int t) {                    /* split hi/lo, store both tiles */
        float* st = smem + (t & 1) * STG_FLOATS;
#pragma unroll
        for (int c = 0; c < 4; ++c) {
            uint4 h, l;
            split_tf32(pa[c].x, h.x, l.x); split_tf32(pa[c].y, h.y, l.y);
            split_tf32(pa[c].z, h.z, l.z); split_tf32(pa[c].w, h.w, l.w);
            *(uint4*)(st + OFF_AH + sbase + c * 4) = h;
            *(uint4*)(st + OFF_AL + sbase + c * 4) = l;
        }
    };

    float acc[4][4][4];
#pragma unroll
    for (int i = 0; i < 4; ++i)
#pragma unroll
        for (int j = 0; j < 4; ++j) {
            acc[i][j][0] = 0.f; acc[i][j][1] = 0.f;
            acc[i][j][2] = 0.f; acc[i][j][3] = 0.f;
        }

    const int lr = lane >> 2;   /* 0..7 */
    const int lc = lane & 3;    /* 0..3 */

    /* prologue */
    issueB(0);
    ldgA(0);
    stsA(0);
    CP_WAIT0();
    __syncthreads();

    for (int t = 0; t < NCH; ++t) {
        if (t + 1 < NCH) { issueB(t + 1); ldgA(t + 1); }

        const float*    stg = smem + (t & 1) * STG_FLOATS;
        const uint32_t* AsH = (const uint32_t*)(stg + OFF_AH);
        const uint32_t* AsL = (const uint32_t*)(stg + OFF_AL);
        const float*    Bs  = stg + OFF_B;

#pragma unroll
        for (int ks = 0; ks < 4; ++ks) {
            const int kb = ks * 8;
            /* A fragments: pre-split, no ALU */
            uint32_t ah[4][4], al[4][4];
#pragma unroll
            for (int mt = 0; mt < 4; ++mt) {
                const int r0 = wm * 64 + mt * 16 + lr;
                const int i00 = r0 * LDSW + kb + lc;
                const int i10 = (r0 + 8) * LDSW + kb + lc;
                ah[mt][0] = AsH[i00];     al[mt][0] = AsL[i00];
                ah[mt][1] = AsH[i10];     al[mt][1] = AsL[i10];
                ah[mt][2] = AsH[i00 + 4]; al[mt][2] = AsL[i00 + 4];
                ah[mt][3] = AsH[i10 + 4]; al[mt][3] = AsL[i10 + 4];
            }
#pragma unroll
            for (int nt = 0; nt < 4; ++nt) {
                const int nr = wn * 32 + nt * 8 + lr;
                const int j0 = nr * LDSW + kb + lc;
                /* B raw fp32 -> split in registers (2x reuse only) */
                const float u0 = Bs[j0];
                const float u1 = Bs[j0 + 4];
                uint32_t bh0, bl0, bh1, bl1;
                split_tf32(u0, bh0, bl0);
                split_tf32(u1, bh1, bl1);
                /* term-outer, mt-inner: consecutive MMAs hit different accs */
#pragma unroll
                for (int mt = 0; mt < 4; ++mt) mma8(acc[mt][nt], ah[mt], bh0, bh1);
#pragma unroll
                for (int mt = 0; mt < 4; ++mt) mma8(acc[mt][nt], al[mt], bh0, bh1);
#pragma unroll
                for (int mt = 0; mt < 4; ++mt) mma8(acc[mt][nt], ah[mt], bl0, bl1);
            }
        }

        if (t + 1 < NCH) {
            stsA(t + 1);        /* other buffer: safe, readers of t done below */
            CP_WAIT0();         /* B(t+1) landed */
        }
        __syncthreads();
    }

    /* ---------------- epilogue: bias + store ---------------- */
#pragma unroll
    for (int mt = 0; mt < 4; ++mt) {
        const int r = row0 + wm * 64 + mt * 16 + lr;
#pragma unroll
        for (int nt = 0; nt < 4; ++nt) {
            const int nloc = wn * 32 + nt * 8 + lc * 2;
            const float bx = bias[nloc];
            const float by = bias[nloc + 1];
            float2 o0, o1;
            o0.x = acc[mt][nt][0] + bx; o0.y = acc[mt][nt][1] + by;
            o1.x = acc[mt][nt][2] + bx; o1.y = acc[mt][nt][3] + by;
            *(float2*)(dst + (size_t)r * F + n0 + nloc)       = o0;
            *(float2*)(dst + (size_t)(r + 8) * F + n0 + nloc) = o1;
        }
    }
}

/* ------------------------------ host ------------------------------ */
extern "C" void kernel_launch(void* const* d_in, const int* in_sizes, int n_in,
                              void* d_out, int out_size)
{
    const float* x    = (const float*)d_in[0];
    const float* Wbig = (const float*)d_in[1];
    const float* Bbig = (const float*)d_in[2];
    const float* Wlil = (const float*)d_in[3];
    const float* Blil = (const float*)d_in[4];
    float* out = (float*)d_out;

    float *ping, *pong, *wt;
    cudaGetSymbolAddress((void**)&ping, g_ping);
    cudaGetSymbolAddress((void**)&pong, g_pong);
    cudaGetSymbolAddress((void**)&wt, g_WT);

    cudaFuncSetAttribute(layer_kernel,
                         cudaFuncAttributeMaxDynamicSharedMemorySize, SMEM_DYN);

    transpose_wbig<<<dim3(16, 16, 8), dim3(32, 8)>>>(Wbig, wt);

    dim3 grid(MTOT / BM, F / BN);   /* 256 x 4 */
    for (int l = 0; l < NLAYERS; ++l) {
        const float* s = (l == 0) ? x : ((l & 1) ? ping : pong);
        float* d = (l == NLAYERS - 1) ? out : ((l & 1) ? pong : ping);
        layer_kernel<<<grid, 256, SMEM_DYN>>>(s, d, wt, Bbig, Wlil, Blil, l);
    }
}